// round 1
// baseline (speedup 1.0000x reference)
#include <cuda_runtime.h>
#include <math.h>
#include <stdint.h>

// Problem shapes (fixed by the dataset)
constexpr int Bb = 16;    // batch
constexpr int Ss = 2048;  // tokens
constexpr int Dd = 512;   // dim
constexpr int Mm = 256;   // memory slots
constexpr int Rr = 64;    // low rank
constexpr float EPS = 1e-5f;
constexpr float STATE_MASS = 4.0f;
constexpr float LRS = 0.1f;

// ---------------- scratch (static device globals; no allocs) ----------------
__device__ float g_scores[(size_t)Bb * Mm * Ss];   // 33.5 MB  [b][m][s]
__device__ float g_ps[(size_t)Bb * Ss * Rr];       // 8.4 MB   [b*S+s][r]
__device__ float g_mem_val0[(size_t)Mm * Dd];      // LN(init_val), batch-independent
__device__ float g_pt2[(size_t)Mm * Rr];           // (mem_val0@rUt + b) * r_w * 0.1
__device__ float g_mem_state0[Mm];                 // signed-softmax-state(init_state)
__device__ float g_mem_val1[(size_t)Bb * Mm * Dd]; // post-write, post-LN
__device__ float g_state1_raw[(size_t)Bb * Mm];
__device__ float g_state1[(size_t)Bb * Mm];
__device__ float g_qt[(size_t)Bb * Mm * Rr];       // (mem_val1@pUt + b) * p_w * 0.1
__device__ float g_qs2[(size_t)Bb * Mm * Rr];      // (mem_val1@pUs + b) * state1[b,j]

// ---------------- shared helpers ----------------
// Block of 256 threads; each thread contributes 2 values (a0, a1) of a 512-long row.
// swr must be >= 18 floats of shared memory.
__device__ __forceinline__ void block_ln_512(float a0, float a1, float& mu, float& ri,
                                             float* swr) {
    float ps = a0 + a1;
    float pq = fmaf(a0, a0, a1 * a1);
#pragma unroll
    for (int off = 16; off; off >>= 1) {
        ps += __shfl_down_sync(0xffffffffu, ps, off);
        pq += __shfl_down_sync(0xffffffffu, pq, off);
    }
    int tid = threadIdx.x, wid = tid >> 5, lane = tid & 31;
    if (lane == 0) { swr[wid] = ps; swr[8 + wid] = pq; }
    __syncthreads();
    if (tid == 0) {
        float s = 0.f, q = 0.f;
#pragma unroll
        for (int i = 0; i < 8; i++) { s += swr[i]; q += swr[8 + i]; }
        float m = s * (1.0f / 512.0f);
        float v = q * (1.0f / 512.0f) - m * m;
        swr[16] = m;
        swr[17] = rsqrtf(v + EPS);
    }
    __syncthreads();
    mu = swr[16];
    ri = swr[17];
}

// ---------------- kernel: LayerNorm rows (row length 512) ----------------
__global__ void ln_rows_kernel(const float* __restrict__ in, float* __restrict__ out,
                               const float* __restrict__ g, const float* __restrict__ bta) {
    __shared__ float swr[18];
    int row = blockIdx.x, tid = threadIdx.x;
    const float* x = in + (size_t)row * Dd;
    float a0 = x[tid], a1 = x[tid + 256];
    float mu, ri;
    block_ln_512(a0, a1, mu, ri, swr);
    float* o = out + (size_t)row * Dd;
    o[tid]       = (a0 - mu) * ri * g[tid] + bta[tid];
    o[tid + 256] = (a1 - mu) * ri * g[tid + 256] + bta[tid + 256];
}

// ---------------- kernel: signed softmax state over 256 slots ----------------
__global__ void sss_kernel(const float* __restrict__ in, float* __restrict__ out) {
    int tid = threadIdx.x;
    const float* x = in + (size_t)blockIdx.x * Mm;
    float v = x[tid];
    float a = fabsf(v);
    __shared__ float swr[8];
    __shared__ float s_bc[2];
    int wid = tid >> 5, lane = tid & 31;
    float m = a;
#pragma unroll
    for (int off = 16; off; off >>= 1) m = fmaxf(m, __shfl_down_sync(0xffffffffu, m, off));
    if (lane == 0) swr[wid] = m;
    __syncthreads();
    if (tid == 0) {
        float mm = swr[0];
#pragma unroll
        for (int i = 1; i < 8; i++) mm = fmaxf(mm, swr[i]);
        s_bc[0] = mm;
    }
    __syncthreads();
    float e = expf(a - s_bc[0]);
    float s = e;
#pragma unroll
    for (int off = 16; off; off >>= 1) s += __shfl_down_sync(0xffffffffu, s, off);
    __syncthreads();
    if (lane == 0) swr[wid] = s;
    __syncthreads();
    if (tid == 0) {
        float ss = 0.f;
#pragma unroll
        for (int i = 0; i < 8; i++) ss += swr[i];
        s_bc[1] = ss;
    }
    __syncthreads();
    float sgn = (v > 0.f) ? 1.f : ((v < 0.f) ? -1.f : 0.f);
    out[(size_t)blockIdx.x * Mm + tid] = sgn * e / s_bc[1] * STATE_MASS;
}

// ---------------- kernel: projection X[rows,512] @ W[512,64] + bias ----------------
// 16 rows per block, 256 threads. thread: 4 consecutive r, 1 row.
// out[row][r] = (dot + bias[r]) * (rscale ? rscale[r]*0.1 : 1) * (rowscale ? rowscale[row] : 1)
__global__ __launch_bounds__(256) void proj_kernel(
    const float* __restrict__ X, float* __restrict__ out,
    const float* __restrict__ W, const float* __restrict__ bias,
    const float* __restrict__ rscale, const float* __restrict__ rowscale) {
    __shared__ float4 Xs[16][128];  // 16 rows x 512 floats = 32 KB
    int tid = threadIdx.x;
    int row0 = blockIdx.x * 16;
    const float4* Xg = (const float4*)(X + (size_t)row0 * Dd);
    float4* Xl = &Xs[0][0];
#pragma unroll
    for (int i = 0; i < 8; i++) Xl[tid + 256 * i] = Xg[tid + 256 * i];
    __syncthreads();

    int r4 = (tid & 15) * 4;
    int sr = tid >> 4;
    float4 acc = make_float4(0.f, 0.f, 0.f, 0.f);
#pragma unroll 4
    for (int d4 = 0; d4 < 128; d4++) {
        float4 xv = Xs[sr][d4];
        const float* Wp = W + (size_t)(d4 * 4) * Rr + r4;
        float4 w0 = *(const float4*)(Wp);
        float4 w1 = *(const float4*)(Wp + Rr);
        float4 w2 = *(const float4*)(Wp + 2 * Rr);
        float4 w3 = *(const float4*)(Wp + 3 * Rr);
        acc.x = fmaf(xv.x, w0.x, fmaf(xv.y, w1.x, fmaf(xv.z, w2.x, fmaf(xv.w, w3.x, acc.x))));
        acc.y = fmaf(xv.x, w0.y, fmaf(xv.y, w1.y, fmaf(xv.z, w2.y, fmaf(xv.w, w3.y, acc.y))));
        acc.z = fmaf(xv.x, w0.z, fmaf(xv.y, w1.z, fmaf(xv.z, w2.z, fmaf(xv.w, w3.z, acc.z))));
        acc.w = fmaf(xv.x, w0.w, fmaf(xv.y, w1.w, fmaf(xv.z, w2.w, fmaf(xv.w, w3.w, acc.w))));
    }
    float rowsc = rowscale ? rowscale[row0 + sr] : 1.f;
    float4 bv = *(const float4*)(bias + r4);
    float s0 = rowsc, s1 = rowsc, s2 = rowsc, s3 = rowsc;
    if (rscale) {
        float4 rv = *(const float4*)(rscale + r4);
        s0 *= rv.x * LRS; s1 *= rv.y * LRS; s2 *= rv.z * LRS; s3 *= rv.w * LRS;
    }
    float4 o;
    o.x = (acc.x + bv.x) * s0;
    o.y = (acc.y + bv.y) * s1;
    o.z = (acc.z + bv.z) * s2;
    o.w = (acc.w + bv.w) * s3;
    *(float4*)(out + (size_t)(row0 + sr) * Rr + r4) = o;
}

// ---------------- kernel: scores[b][m][s] = sum_r pt2[m][r] * ps[b][s][r] ----------------
// grid (S/64, B). 256 threads. thread tile: 8 m x 8 s (consecutive s).
__global__ __launch_bounds__(256) void scores_kernel() {
    __shared__ float psm[64 * 68];  // [s][r], row stride 68 floats (16B aligned, conflict-free)
    int b = blockIdx.y;
    int s0 = blockIdx.x * 64;
    int tid = threadIdx.x;
    const float* psg = g_ps + ((size_t)b * Ss + s0) * Rr;
#pragma unroll
    for (int it = 0; it < 16; it++) {
        int i = tid + 256 * it;
        int s = i >> 6, r = i & 63;
        psm[s * 68 + r] = psg[i];
    }
    __syncthreads();

    int sg = (tid & 7) * 8;
    int mg = (tid >> 3) * 8;
    float acc[8][8];
#pragma unroll
    for (int i = 0; i < 8; i++)
#pragma unroll
        for (int j = 0; j < 8; j++) acc[i][j] = 0.f;

#pragma unroll
    for (int r4 = 0; r4 < Rr; r4 += 4) {
        float4 ptv[8];
#pragma unroll
        for (int mm = 0; mm < 8; mm++)
            ptv[mm] = *(const float4*)&g_pt2[(size_t)(mg + mm) * Rr + r4];
#pragma unroll
        for (int ss = 0; ss < 8; ss++) {
            float4 pv = *(const float4*)&psm[(sg + ss) * 68 + r4];
#pragma unroll
            for (int mm = 0; mm < 8; mm++) {
                acc[mm][ss] = fmaf(ptv[mm].x, pv.x,
                               fmaf(ptv[mm].y, pv.y,
                                 fmaf(ptv[mm].z, pv.z,
                                   fmaf(ptv[mm].w, pv.w, acc[mm][ss]))));
            }
        }
    }
#pragma unroll
    for (int mm = 0; mm < 8; mm++) {
        float* o = g_scores + ((size_t)(b * Mm + mg + mm)) * Ss + s0 + sg;
        *(float4*)(o)     = make_float4(acc[mm][0], acc[mm][1], acc[mm][2], acc[mm][3]);
        *(float4*)(o + 4) = make_float4(acc[mm][4], acc[mm][5], acc[mm][6], acc[mm][7]);
    }
}

// ---------------- kernel: write phase (top-16 over S, edges, gather-add, LN) ----------------
__global__ __launch_bounds__(256) void write_kernel(
    const float* __restrict__ token_val, const float* __restrict__ token_state,
    const float* __restrict__ ln_g, const float* __restrict__ ln_b) {
    int bm = blockIdx.x;
    int b = bm >> 8, m = bm & 255;
    int tid = threadIdx.x, w = tid >> 5, lane = tid & 31;
    __shared__ float s_cab[128];
    __shared__ int s_cidx[128];
    __shared__ float s_edge[16];
    __shared__ int s_eidx[16];
    __shared__ float swr[18];

    const float* row = g_scores + (size_t)bm * Ss;

    // per-warp top-16 of its 256-element chunk
    {
        int base = w * 256 + lane;
        float va[8];
#pragma unroll
        for (int j = 0; j < 8; j++) va[j] = fabsf(row[base + 32 * j]);
        for (int p = 0; p < 16; p++) {
            float best = -1.f;
            int bj = 0;
#pragma unroll
            for (int j = 0; j < 8; j++)
                if (va[j] > best) { best = va[j]; bj = j; }
            int bidx = base + 32 * bj;
#pragma unroll
            for (int off = 16; off; off >>= 1) {
                float ob = __shfl_down_sync(0xffffffffu, best, off);
                int oi = __shfl_down_sync(0xffffffffu, bidx, off);
                if (ob > best || (ob == best && oi < bidx)) { best = ob; bidx = oi; }
            }
            best = __shfl_sync(0xffffffffu, best, 0);
            bidx = __shfl_sync(0xffffffffu, bidx, 0);
#pragma unroll
            for (int j = 0; j < 8; j++)
                if (base + 32 * j == bidx) va[j] = -1.f;
            if (lane == 0) { s_cab[w * 16 + p] = best; s_cidx[w * 16 + p] = bidx; }
        }
    }
    __syncthreads();

    // warp 0 merges the 128 candidates into global top-16, computes edges + state
    if (w == 0) {
        float va[4];
        int gi[4];
#pragma unroll
        for (int j = 0; j < 4; j++) {
            int sl = lane + 32 * j;
            va[j] = s_cab[sl];
            gi[j] = s_cidx[sl];
        }
        float myabs = 0.f;
        int myidx = 0;
        for (int p = 0; p < 16; p++) {
            float best = -1.f;
            int bidx = 0x7fffffff, bsl = -1;
#pragma unroll
            for (int j = 0; j < 4; j++) {
                if (va[j] > best || (va[j] == best && gi[j] < bidx)) {
                    best = va[j]; bidx = gi[j]; bsl = lane + 32 * j;
                }
            }
#pragma unroll
            for (int off = 16; off; off >>= 1) {
                float ob = __shfl_down_sync(0xffffffffu, best, off);
                int oi = __shfl_down_sync(0xffffffffu, bidx, off);
                int os = __shfl_down_sync(0xffffffffu, bsl, off);
                if (ob > best || (ob == best && oi < bidx)) { best = ob; bidx = oi; bsl = os; }
            }
            best = __shfl_sync(0xffffffffu, best, 0);
            bidx = __shfl_sync(0xffffffffu, bidx, 0);
            bsl = __shfl_sync(0xffffffffu, bsl, 0);
#pragma unroll
            for (int j = 0; j < 4; j++)
                if (lane + 32 * j == bsl) va[j] = -1.f;
            if (lane == p) { myabs = best; myidx = bidx; }
        }
        float maxa = __shfl_sync(0xffffffffu, myabs, 0);
        bool valid = lane < 16;
        float sel = valid ? row[myidx] : 0.f;
        float e = valid ? expf(myabs - maxa) : 0.f;
        float sum = e;
#pragma unroll
        for (int off = 16; off; off >>= 1) sum += __shfl_xor_sync(0xffffffffu, sum, off);
        float sgn = (sel > 0.f) ? 1.f : ((sel < 0.f) ? -1.f : 0.f);
        float edge = sgn * e / sum;
        if (valid) { s_edge[lane] = edge; s_eidx[lane] = myidx; }
        float c = valid ? edge * token_state[(size_t)b * Ss + myidx] : 0.f;
#pragma unroll
        for (int off = 16; off; off >>= 1) c += __shfl_xor_sync(0xffffffffu, c, off);
        if (lane == 0) g_state1_raw[bm] = g_mem_state0[m] + c;
    }
    __syncthreads();

    // value update + LN
    int d = tid;
    float a0 = g_mem_val0[(size_t)m * Dd + d];
    float a1 = g_mem_val0[(size_t)m * Dd + d + 256];
#pragma unroll
    for (int k = 0; k < 16; k++) {
        const float* tv = token_val + ((size_t)b * Ss + s_eidx[k]) * Dd;
        float ek = s_edge[k];
        a0 = fmaf(ek, tv[d], a0);
        a1 = fmaf(ek, tv[d + 256], a1);
    }
    float mu, ri;
    block_ln_512(a0, a1, mu, ri, swr);
    float* o = g_mem_val1 + (size_t)bm * Dd;
    o[d]       = (a0 - mu) * ri * ln_g[d] + ln_b[d];
    o[d + 256] = (a1 - mu) * ri * ln_g[d + 256] + ln_b[d + 256];
}

// ---------------- kernel: propagation (pscores row, top-16, residual, final LN) ----------------
__global__ __launch_bounds__(256) void prop_kernel(
    float* __restrict__ out_final, const float* __restrict__ ln_g,
    const float* __restrict__ ln_b) {
    int bi = blockIdx.x;
    int b = bi >> 8;
    int tid = threadIdx.x, w = tid >> 5, lane = tid & 31;
    __shared__ float s_qt[64];
    __shared__ float s_prow[256];
    __shared__ float s_edge[16];
    __shared__ int s_eidx[16];
    __shared__ float swr[18];

    if (tid < 64) s_qt[tid] = g_qt[(size_t)bi * Rr + tid];
    __syncthreads();

    // pscores row: prow[j] = dot(qt_i, qs2[b,j,:])  (state weight folded into qs2)
    {
        const float* q = g_qs2 + ((size_t)(b * Mm) + tid) * Rr;
        float acc = 0.f;
#pragma unroll
        for (int r = 0; r < Rr; r += 4) {
            float4 qv = *(const float4*)(q + r);
            acc = fmaf(qv.x, s_qt[r], acc);
            acc = fmaf(qv.y, s_qt[r + 1], acc);
            acc = fmaf(qv.z, s_qt[r + 2], acc);
            acc = fmaf(qv.w, s_qt[r + 3], acc);
        }
        s_prow[tid] = acc;
    }
    __syncthreads();

    if (w == 0) {
        float va[8];
#pragma unroll
        for (int j = 0; j < 8; j++) va[j] = fabsf(s_prow[lane + 32 * j]);
        float myabs = 0.f;
        int myidx = 0;
        for (int p = 0; p < 16; p++) {
            float best = -1.f;
            int bj = 0;
#pragma unroll
            for (int j = 0; j < 8; j++)
                if (va[j] > best) { best = va[j]; bj = j; }
            int bidx = lane + 32 * bj;
#pragma unroll
            for (int off = 16; off; off >>= 1) {
                float ob = __shfl_down_sync(0xffffffffu, best, off);
                int oi = __shfl_down_sync(0xffffffffu, bidx, off);
                if (ob > best || (ob == best && oi < bidx)) { best = ob; bidx = oi; }
            }
            best = __shfl_sync(0xffffffffu, best, 0);
            bidx = __shfl_sync(0xffffffffu, bidx, 0);
#pragma unroll
            for (int j = 0; j < 8; j++)
                if (lane + 32 * j == bidx) va[j] = -1.f;
            if (lane == p) { myabs = best; myidx = bidx; }
        }
        float maxa = __shfl_sync(0xffffffffu, myabs, 0);
        bool valid = lane < 16;
        float sel = valid ? s_prow[myidx] : 0.f;
        float e = valid ? expf(myabs - maxa) : 0.f;
        float sum = e;
#pragma unroll
        for (int off = 16; off; off >>= 1) sum += __shfl_xor_sync(0xffffffffu, sum, off);
        float sgn = (sel > 0.f) ? 1.f : ((sel < 0.f) ? -1.f : 0.f);
        float edge = sgn * e / sum;
        if (valid) { s_edge[lane] = edge; s_eidx[lane] = myidx; }
    }
    __syncthreads();

    int d = tid;
    float a0 = g_mem_val1[(size_t)bi * Dd + d];
    float a1 = g_mem_val1[(size_t)bi * Dd + d + 256];
#pragma unroll
    for (int k = 0; k < 16; k++) {
        const float* mv = g_mem_val1 + ((size_t)(b * Mm + s_eidx[k])) * Dd;
        float ek = s_edge[k];
        a0 = fmaf(ek, mv[d], a0);
        a1 = fmaf(ek, mv[d + 256], a1);
    }
    float mu, ri;
    block_ln_512(a0, a1, mu, ri, swr);
    float* o = out_final + (size_t)bi * Dd;
    o[d]       = (a0 - mu) * ri * ln_g[d] + ln_b[d];
    o[d + 256] = (a1 - mu) * ri * ln_g[d + 256] + ln_b[d + 256];
}

// ---------------- host launch ----------------
extern "C" void kernel_launch(void* const* d_in, const int* in_sizes, int n_in,
                              void* d_out, int out_size) {
    (void)in_sizes; (void)n_in; (void)out_size;
    const float* token_val   = (const float*)d_in[0];
    const float* token_state = (const float*)d_in[1];
    const float* init_state  = (const float*)d_in[2];
    const float* init_val    = (const float*)d_in[3];
    const float* rUs_w = (const float*)d_in[4];
    const float* rUs_b = (const float*)d_in[5];
    const float* rUt_w = (const float*)d_in[6];
    const float* rUt_b = (const float*)d_in[7];
    const float* r_w   = (const float*)d_in[8];
    const float* pUs_w = (const float*)d_in[9];
    const float* pUs_b = (const float*)d_in[10];
    const float* pUt_w = (const float*)d_in[11];
    const float* pUt_b = (const float*)d_in[12];
    const float* p_w   = (const float*)d_in[13];
    const float* ln_g  = (const float*)d_in[14];
    const float* ln_b  = (const float*)d_in[15];
    float* out = (float*)d_out;

    float *p_mv0, *p_pt2, *p_ps, *p_mv1, *p_qt, *p_qs2, *p_st0, *p_st1raw, *p_st1;
    cudaGetSymbolAddress((void**)&p_mv0, g_mem_val0);
    cudaGetSymbolAddress((void**)&p_pt2, g_pt2);
    cudaGetSymbolAddress((void**)&p_ps, g_ps);
    cudaGetSymbolAddress((void**)&p_mv1, g_mem_val1);
    cudaGetSymbolAddress((void**)&p_qt, g_qt);
    cudaGetSymbolAddress((void**)&p_qs2, g_qs2);
    cudaGetSymbolAddress((void**)&p_st0, g_mem_state0);
    cudaGetSymbolAddress((void**)&p_st1raw, g_state1_raw);
    cudaGetSymbolAddress((void**)&p_st1, g_state1);

    // mem_val0 = LN(init_val)  (batch independent)
    ln_rows_kernel<<<Mm, 256>>>(init_val, p_mv0, ln_g, ln_b);
    // mem_state0 = signed_softmax_state(init_state)
    sss_kernel<<<1, 256>>>(init_state, p_st0);
    // pt2 = (mem_val0 @ rUt + b) * r_w * 0.1
    proj_kernel<<<Mm / 16, 256>>>(p_mv0, p_pt2, rUt_w, rUt_b, r_w, nullptr);
    // ps = token_val @ rUs + b
    proj_kernel<<<(Bb * Ss) / 16, 256>>>(token_val, p_ps, rUs_w, rUs_b, nullptr, nullptr);
    // scores = pt2 . ps
    scores_kernel<<<dim3(Ss / 64, Bb), 256>>>();
    // write phase: topk + edges + gather-add + LN; also raw state update
    write_kernel<<<Bb * Mm, 256>>>(token_val, token_state, ln_g, ln_b);
    // state1 = signed_softmax_state(state1_raw)
    sss_kernel<<<Bb, 256>>>(p_st1raw, p_st1);
    // qt = (mem_val1 @ pUt + b) * p_w * 0.1 ;  qs2 = (mem_val1 @ pUs + b) * state1[row]
    proj_kernel<<<(Bb * Mm) / 16, 256>>>(p_mv1, p_qt, pUt_w, pUt_b, p_w, nullptr);
    proj_kernel<<<(Bb * Mm) / 16, 256>>>(p_mv1, p_qs2, pUs_w, pUs_b, nullptr, p_st1);
    // propagation + final LN -> out
    prop_kernel<<<Bb * Mm, 256>>>(out, ln_g, ln_b);
}

// round 2
// speedup vs baseline: 1.6280x; 1.6280x over previous
#include <cuda_runtime.h>
#include <math.h>
#include <stdint.h>

// Problem shapes (fixed by the dataset)
constexpr int Bb = 16;    // batch
constexpr int Ss = 2048;  // tokens
constexpr int Dd = 512;   // dim
constexpr int Mm = 256;   // memory slots
constexpr int Rr = 64;    // low rank
constexpr float EPS = 1e-5f;
constexpr float STATE_MASS = 4.0f;
constexpr float LRS = 0.1f;

// ---------------- scratch (static device globals; no allocs) ----------------
__device__ float g_scores[(size_t)Bb * Mm * Ss];   // 33.5 MB  [b][m][s]
__device__ float g_ps[(size_t)Bb * Ss * Rr];       // 8.4 MB   [b*S+s][r]
__device__ float g_mem_val0[(size_t)Mm * Dd];      // LN(init_val), batch-independent
__device__ float g_pt2[(size_t)Mm * Rr];           // (mem_val0@rUt + b) * r_w * 0.1
__device__ float g_mem_state0[Mm];                 // signed-softmax-state(init_state)
__device__ float g_mem_val1[(size_t)Bb * Mm * Dd]; // post-write, post-LN
__device__ float g_state1_raw[(size_t)Bb * Mm];
__device__ float g_state1[(size_t)Bb * Mm];
__device__ float g_qt[(size_t)Bb * Mm * Rr];       // (mem_val1@pUt + b) * p_w * 0.1
__device__ float g_qs2[(size_t)Bb * Mm * Rr];      // (mem_val1@pUs + b) * state1[b,j]

// ---------------- shared helpers ----------------
__device__ __forceinline__ void block_ln_512(float a0, float a1, float& mu, float& ri,
                                             float* swr) {
    float ps = a0 + a1;
    float pq = fmaf(a0, a0, a1 * a1);
#pragma unroll
    for (int off = 16; off; off >>= 1) {
        ps += __shfl_down_sync(0xffffffffu, ps, off);
        pq += __shfl_down_sync(0xffffffffu, pq, off);
    }
    int tid = threadIdx.x, wid = tid >> 5, lane = tid & 31;
    if (lane == 0) { swr[wid] = ps; swr[8 + wid] = pq; }
    __syncthreads();
    if (tid == 0) {
        float s = 0.f, q = 0.f;
#pragma unroll
        for (int i = 0; i < 8; i++) { s += swr[i]; q += swr[8 + i]; }
        float m = s * (1.0f / 512.0f);
        float v = q * (1.0f / 512.0f) - m * m;
        swr[16] = m;
        swr[17] = rsqrtf(v + EPS);
    }
    __syncthreads();
    mu = swr[16];
    ri = swr[17];
}

// ---------------- kernel: LayerNorm rows (row length 512) ----------------
__global__ void ln_rows_kernel(const float* __restrict__ in, float* __restrict__ out,
                               const float* __restrict__ g, const float* __restrict__ bta) {
    __shared__ float swr[18];
    int row = blockIdx.x, tid = threadIdx.x;
    const float* x = in + (size_t)row * Dd;
    float a0 = x[tid], a1 = x[tid + 256];
    float mu, ri;
    block_ln_512(a0, a1, mu, ri, swr);
    float* o = out + (size_t)row * Dd;
    o[tid]       = (a0 - mu) * ri * g[tid] + bta[tid];
    o[tid + 256] = (a1 - mu) * ri * g[tid + 256] + bta[tid + 256];
}

// ---------------- kernel: signed softmax state over 256 slots ----------------
__global__ void sss_kernel(const float* __restrict__ in, float* __restrict__ out) {
    int tid = threadIdx.x;
    const float* x = in + (size_t)blockIdx.x * Mm;
    float v = x[tid];
    float a = fabsf(v);
    __shared__ float swr[8];
    __shared__ float s_bc[2];
    int wid = tid >> 5, lane = tid & 31;
    float m = a;
#pragma unroll
    for (int off = 16; off; off >>= 1) m = fmaxf(m, __shfl_down_sync(0xffffffffu, m, off));
    if (lane == 0) swr[wid] = m;
    __syncthreads();
    if (tid == 0) {
        float mm = swr[0];
#pragma unroll
        for (int i = 1; i < 8; i++) mm = fmaxf(mm, swr[i]);
        s_bc[0] = mm;
    }
    __syncthreads();
    float e = expf(a - s_bc[0]);
    float s = e;
#pragma unroll
    for (int off = 16; off; off >>= 1) s += __shfl_down_sync(0xffffffffu, s, off);
    __syncthreads();
    if (lane == 0) swr[wid] = s;
    __syncthreads();
    if (tid == 0) {
        float ss = 0.f;
#pragma unroll
        for (int i = 0; i < 8; i++) ss += swr[i];
        s_bc[1] = ss;
    }
    __syncthreads();
    float sgn = (v > 0.f) ? 1.f : ((v < 0.f) ? -1.f : 0.f);
    out[(size_t)blockIdx.x * Mm + tid] = sgn * e / s_bc[1] * STATE_MASS;
}

// ---------------- tiled projection GEMM: out[rows,64] = X[rows,512] @ W[512,64] ----------------
// Block tile RT rows x 64 cols, K chunks of 16 staged in smem (X transposed).
// Thread tile (RT/16) rows x 4 cols. 256 threads.
// blockIdx.y selects parameter set (for fused dual-projection launches).
// out[row][c] = (dot + bias[c]) * (rs ? rs[c]*0.1 : 1) * (rowsc ? rowsc[row] : 1)
template <int RT>
__global__ __launch_bounds__(256) void gemm_proj(
    const float* __restrict__ X,
    float* __restrict__ out0, const float* __restrict__ W0, const float* __restrict__ b0,
    const float* __restrict__ rs0, const float* __restrict__ rowsc0,
    float* __restrict__ out1, const float* __restrict__ W1, const float* __restrict__ b1,
    const float* __restrict__ rs1, const float* __restrict__ rowsc1) {
    constexpr int RPT = RT / 16;       // rows per thread
    constexpr int XSTR = RT + 4;       // padded smem stride (floats); (RT+4)*4B is 16B-mult
    __shared__ float sx[16 * XSTR];
    __shared__ float sw[16 * 68];

    int tid = threadIdx.x;
    int row0 = blockIdx.x * RT;
    int set = blockIdx.y;
    const float* W     = set ? W1 : W0;
    const float* bias  = set ? b1 : b0;
    const float* rs    = set ? rs1 : rs0;
    const float* rowsc = set ? rowsc1 : rowsc0;
    float* out         = set ? out1 : out0;

    int rowg = tid >> 4;       // 16 row groups
    int colg = tid & 15;       // 16 col groups x 4 cols

    float acc[RPT][4];
#pragma unroll
    for (int r = 0; r < RPT; r++)
#pragma unroll
        for (int c = 0; c < 4; c++) acc[r][c] = 0.f;

    for (int k0 = 0; k0 < Dd; k0 += 16) {
        // stage X chunk transposed: sx[k][row]
        constexpr int NV = RT * 16 / 4;  // float4 count
#pragma unroll
        for (int t = 0; t < (NV + 255) / 256; t++) {
            int f = tid + 256 * t;
            if ((NV % 256 == 0) || (f < NV)) {
                int row = f >> 2, q = f & 3;
                float4 v = *(const float4*)&X[(size_t)(row0 + row) * Dd + k0 + 4 * q];
                sx[(4 * q + 0) * XSTR + row] = v.x;
                sx[(4 * q + 1) * XSTR + row] = v.y;
                sx[(4 * q + 2) * XSTR + row] = v.z;
                sx[(4 * q + 3) * XSTR + row] = v.w;
            }
        }
        // stage W chunk: sw[k][col], 256 float4
        {
            int k = tid >> 4, c = tid & 15;
            float4 v = *(const float4*)&W[(size_t)(k0 + k) * Rr + 4 * c];
            *(float4*)&sw[k * 68 + 4 * c] = v;
        }
        __syncthreads();
#pragma unroll
        for (int kk = 0; kk < 16; kk++) {
            float4 wv = *(const float4*)&sw[kk * 68 + colg * 4];
            float xr[RPT];
            if constexpr (RPT == 8) {
                float4 x0 = *(const float4*)&sx[kk * XSTR + rowg * 8];
                float4 x1 = *(const float4*)&sx[kk * XSTR + rowg * 8 + 4];
                xr[0] = x0.x; xr[1] = x0.y; xr[2] = x0.z; xr[3] = x0.w;
                xr[4] = x1.x; xr[5] = x1.y; xr[6] = x1.z; xr[7] = x1.w;
            } else {
                float2 x0 = *(const float2*)&sx[kk * XSTR + rowg * RPT];
                xr[0] = x0.x; xr[1] = x0.y;
            }
#pragma unroll
            for (int r = 0; r < RPT; r++) {
                acc[r][0] = fmaf(xr[r], wv.x, acc[r][0]);
                acc[r][1] = fmaf(xr[r], wv.y, acc[r][1]);
                acc[r][2] = fmaf(xr[r], wv.z, acc[r][2]);
                acc[r][3] = fmaf(xr[r], wv.w, acc[r][3]);
            }
        }
        __syncthreads();
    }

    float4 bv = *(const float4*)&bias[colg * 4];
    float s0 = 1.f, s1 = 1.f, s2 = 1.f, s3 = 1.f;
    if (rs) {
        float4 rv = *(const float4*)&rs[colg * 4];
        s0 = rv.x * LRS; s1 = rv.y * LRS; s2 = rv.z * LRS; s3 = rv.w * LRS;
    }
#pragma unroll
    for (int r = 0; r < RPT; r++) {
        int row = row0 + rowg * RPT + r;
        float rsc = rowsc ? rowsc[row] : 1.f;
        float4 o;
        o.x = (acc[r][0] + bv.x) * s0 * rsc;
        o.y = (acc[r][1] + bv.y) * s1 * rsc;
        o.z = (acc[r][2] + bv.z) * s2 * rsc;
        o.w = (acc[r][3] + bv.w) * s3 * rsc;
        *(float4*)&out[(size_t)row * Rr + colg * 4] = o;
    }
}

// ---------------- tiled scores GEMM: scores[b][m][s] = sum_r pt2[m][r] * ps[b][s][r] ----------------
// Block tile 128 s x 128 m, r chunks of 16 staged transposed in smem. 8x8 thread tile.
// grid (S/128, M/128, B)
__global__ __launch_bounds__(256) void scores2_kernel() {
    __shared__ float sps[16 * 132];  // [r][s]
    __shared__ float spt[16 * 132];  // [r][m]
    int b = blockIdx.z;
    int s0 = blockIdx.x * 128;
    int m0 = blockIdx.y * 128;
    int tid = threadIdx.x;
    int sg = (tid & 15) * 8;
    int mg = (tid >> 4) * 8;

    const float* psg = g_ps + ((size_t)b * Ss + s0) * Rr;
    const float* ptg = g_pt2 + (size_t)m0 * Rr;

    float acc[8][8];
#pragma unroll
    for (int i = 0; i < 8; i++)
#pragma unroll
        for (int j = 0; j < 8; j++) acc[i][j] = 0.f;

    for (int c = 0; c < Rr; c += 16) {
#pragma unroll
        for (int t = 0; t < 2; t++) {
            int f = tid + 256 * t;
            int r = f >> 2, q = f & 3;  // r indexes the 128 rows of each operand tile
            float4 v = *(const float4*)&psg[(size_t)r * Rr + c + 4 * q];
            sps[(4 * q + 0) * 132 + r] = v.x;
            sps[(4 * q + 1) * 132 + r] = v.y;
            sps[(4 * q + 2) * 132 + r] = v.z;
            sps[(4 * q + 3) * 132 + r] = v.w;
            float4 u = *(const float4*)&ptg[(size_t)r * Rr + c + 4 * q];
            spt[(4 * q + 0) * 132 + r] = u.x;
            spt[(4 * q + 1) * 132 + r] = u.y;
            spt[(4 * q + 2) * 132 + r] = u.z;
            spt[(4 * q + 3) * 132 + r] = u.w;
        }
        __syncthreads();
#pragma unroll
        for (int kk = 0; kk < 16; kk++) {
            float4 a0 = *(const float4*)&sps[kk * 132 + sg];
            float4 a1 = *(const float4*)&sps[kk * 132 + sg + 4];
            float4 c0 = *(const float4*)&spt[kk * 132 + mg];
            float4 c1 = *(const float4*)&spt[kk * 132 + mg + 4];
            float sv[8] = {a0.x, a0.y, a0.z, a0.w, a1.x, a1.y, a1.z, a1.w};
            float mv[8] = {c0.x, c0.y, c0.z, c0.w, c1.x, c1.y, c1.z, c1.w};
#pragma unroll
            for (int i = 0; i < 8; i++)
#pragma unroll
                for (int j = 0; j < 8; j++)
                    acc[i][j] = fmaf(mv[i], sv[j], acc[i][j]);
        }
        __syncthreads();
    }
#pragma unroll
    for (int i = 0; i < 8; i++) {
        float* o = g_scores + ((size_t)(b * Mm + m0 + mg + i)) * Ss + s0 + sg;
        *(float4*)(o)     = make_float4(acc[i][0], acc[i][1], acc[i][2], acc[i][3]);
        *(float4*)(o + 4) = make_float4(acc[i][4], acc[i][5], acc[i][6], acc[i][7]);
    }
}

// ---------------- kernel: write phase (top-16 over S, edges, gather-add, LN) ----------------
__global__ __launch_bounds__(256) void write_kernel(
    const float* __restrict__ token_val, const float* __restrict__ token_state,
    const float* __restrict__ ln_g, const float* __restrict__ ln_b) {
    int bm = blockIdx.x;
    int b = bm >> 8, m = bm & 255;
    int tid = threadIdx.x, w = tid >> 5, lane = tid & 31;
    __shared__ float s_cab[128];
    __shared__ int s_cidx[128];
    __shared__ float s_edge[16];
    __shared__ int s_eidx[16];
    __shared__ float swr[18];

    const float* row = g_scores + (size_t)bm * Ss;

    // per-warp top-16 of its 256-element chunk
    {
        int base = w * 256 + lane;
        float va[8];
#pragma unroll
        for (int j = 0; j < 8; j++) va[j] = fabsf(row[base + 32 * j]);
        for (int p = 0; p < 16; p++) {
            float best = -1.f;
            int bj = 0;
#pragma unroll
            for (int j = 0; j < 8; j++)
                if (va[j] > best) { best = va[j]; bj = j; }
            int bidx = base + 32 * bj;
#pragma unroll
            for (int off = 16; off; off >>= 1) {
                float ob = __shfl_down_sync(0xffffffffu, best, off);
                int oi = __shfl_down_sync(0xffffffffu, bidx, off);
                if (ob > best || (ob == best && oi < bidx)) { best = ob; bidx = oi; }
            }
            best = __shfl_sync(0xffffffffu, best, 0);
            bidx = __shfl_sync(0xffffffffu, bidx, 0);
#pragma unroll
            for (int j = 0; j < 8; j++)
                if (base + 32 * j == bidx) va[j] = -1.f;
            if (lane == 0) { s_cab[w * 16 + p] = best; s_cidx[w * 16 + p] = bidx; }
        }
    }
    __syncthreads();

    // warp 0 merges the 128 candidates into global top-16, computes edges + state
    if (w == 0) {
        float va[4];
        int gi[4];
#pragma unroll
        for (int j = 0; j < 4; j++) {
            int sl = lane + 32 * j;
            va[j] = s_cab[sl];
            gi[j] = s_cidx[sl];
        }
        float myabs = 0.f;
        int myidx = 0;
        for (int p = 0; p < 16; p++) {
            float best = -1.f;
            int bidx = 0x7fffffff, bsl = -1;
#pragma unroll
            for (int j = 0; j < 4; j++) {
                if (va[j] > best || (va[j] == best && gi[j] < bidx)) {
                    best = va[j]; bidx = gi[j]; bsl = lane + 32 * j;
                }
            }
#pragma unroll
            for (int off = 16; off; off >>= 1) {
                float ob = __shfl_down_sync(0xffffffffu, best, off);
                int oi = __shfl_down_sync(0xffffffffu, bidx, off);
                int os = __shfl_down_sync(0xffffffffu, bsl, off);
                if (ob > best || (ob == best && oi < bidx)) { best = ob; bidx = oi; bsl = os; }
            }
            best = __shfl_sync(0xffffffffu, best, 0);
            bidx = __shfl_sync(0xffffffffu, bidx, 0);
            bsl = __shfl_sync(0xffffffffu, bsl, 0);
#pragma unroll
            for (int j = 0; j < 4; j++)
                if (lane + 32 * j == bsl) va[j] = -1.f;
            if (lane == p) { myabs = best; myidx = bidx; }
        }
        float maxa = __shfl_sync(0xffffffffu, myabs, 0);
        bool valid = lane < 16;
        float sel = valid ? row[myidx] : 0.f;
        float e = valid ? expf(myabs - maxa) : 0.f;
        float sum = e;
#pragma unroll
        for (int off = 16; off; off >>= 1) sum += __shfl_xor_sync(0xffffffffu, sum, off);
        float sgn = (sel > 0.f) ? 1.f : ((sel < 0.f) ? -1.f : 0.f);
        float edge = sgn * e / sum;
        if (valid) { s_edge[lane] = edge; s_eidx[lane] = myidx; }
        float c = valid ? edge * token_state[(size_t)b * Ss + myidx] : 0.f;
#pragma unroll
        for (int off = 16; off; off >>= 1) c += __shfl_xor_sync(0xffffffffu, c, off);
        if (lane == 0) g_state1_raw[bm] = g_mem_state0[m] + c;
    }
    __syncthreads();

    // value update + LN
    int d = tid;
    float a0 = g_mem_val0[(size_t)m * Dd + d];
    float a1 = g_mem_val0[(size_t)m * Dd + d + 256];
#pragma unroll
    for (int k = 0; k < 16; k++) {
        const float* tv = token_val + ((size_t)b * Ss + s_eidx[k]) * Dd;
        float ek = s_edge[k];
        a0 = fmaf(ek, tv[d], a0);
        a1 = fmaf(ek, tv[d + 256], a1);
    }
    float mu, ri;
    block_ln_512(a0, a1, mu, ri, swr);
    float* o = g_mem_val1 + (size_t)bm * Dd;
    o[d]       = (a0 - mu) * ri * ln_g[d] + ln_b[d];
    o[d + 256] = (a1 - mu) * ri * ln_g[d + 256] + ln_b[d + 256];
}

// ---------------- kernel: propagation (pscores row, top-16, residual, final LN) ----------------
__global__ __launch_bounds__(256) void prop_kernel(
    float* __restrict__ out_final, const float* __restrict__ ln_g,
    const float* __restrict__ ln_b) {
    int bi = blockIdx.x;
    int b = bi >> 8;
    int tid = threadIdx.x, w = tid >> 5, lane = tid & 31;
    __shared__ float s_qt[64];
    __shared__ float s_prow[256];
    __shared__ float s_edge[16];
    __shared__ int s_eidx[16];
    __shared__ float swr[18];

    if (tid < 64) s_qt[tid] = g_qt[(size_t)bi * Rr + tid];
    __syncthreads();

    // pscores row: prow[j] = dot(qt_i, qs2[b,j,:])  (state weight folded into qs2)
    {
        const float* q = g_qs2 + ((size_t)(b * Mm) + tid) * Rr;
        float acc = 0.f;
#pragma unroll
        for (int r = 0; r < Rr; r += 4) {
            float4 qv = *(const float4*)(q + r);
            acc = fmaf(qv.x, s_qt[r], acc);
            acc = fmaf(qv.y, s_qt[r + 1], acc);
            acc = fmaf(qv.z, s_qt[r + 2], acc);
            acc = fmaf(qv.w, s_qt[r + 3], acc);
        }
        s_prow[tid] = acc;
    }
    __syncthreads();

    if (w == 0) {
        float va[8];
#pragma unroll
        for (int j = 0; j < 8; j++) va[j] = fabsf(s_prow[lane + 32 * j]);
        float myabs = 0.f;
        int myidx = 0;
        for (int p = 0; p < 16; p++) {
            float best = -1.f;
            int bj = 0;
#pragma unroll
            for (int j = 0; j < 8; j++)
                if (va[j] > best) { best = va[j]; bj = j; }
            int bidx = lane + 32 * bj;
#pragma unroll
            for (int off = 16; off; off >>= 1) {
                float ob = __shfl_down_sync(0xffffffffu, best, off);
                int oi = __shfl_down_sync(0xffffffffu, bidx, off);
                if (ob > best || (ob == best && oi < bidx)) { best = ob; bidx = oi; }
            }
            best = __shfl_sync(0xffffffffu, best, 0);
            bidx = __shfl_sync(0xffffffffu, bidx, 0);
#pragma unroll
            for (int j = 0; j < 8; j++)
                if (lane + 32 * j == bidx) va[j] = -1.f;
            if (lane == p) { myabs = best; myidx = bidx; }
        }
        float maxa = __shfl_sync(0xffffffffu, myabs, 0);
        bool valid = lane < 16;
        float sel = valid ? s_prow[myidx] : 0.f;
        float e = valid ? expf(myabs - maxa) : 0.f;
        float sum = e;
#pragma unroll
        for (int off = 16; off; off >>= 1) sum += __shfl_xor_sync(0xffffffffu, sum, off);
        float sgn = (sel > 0.f) ? 1.f : ((sel < 0.f) ? -1.f : 0.f);
        float edge = sgn * e / sum;
        if (valid) { s_edge[lane] = edge; s_eidx[lane] = myidx; }
    }
    __syncthreads();

    int d = tid;
    float a0 = g_mem_val1[(size_t)bi * Dd + d];
    float a1 = g_mem_val1[(size_t)bi * Dd + d + 256];
#pragma unroll
    for (int k = 0; k < 16; k++) {
        const float* mv = g_mem_val1 + ((size_t)(b * Mm + s_eidx[k])) * Dd;
        float ek = s_edge[k];
        a0 = fmaf(ek, mv[d], a0);
        a1 = fmaf(ek, mv[d + 256], a1);
    }
    float mu, ri;
    block_ln_512(a0, a1, mu, ri, swr);
    float* o = out_final + (size_t)bi * Dd;
    o[d]       = (a0 - mu) * ri * ln_g[d] + ln_b[d];
    o[d + 256] = (a1 - mu) * ri * ln_g[d + 256] + ln_b[d + 256];
}

// ---------------- host launch ----------------
extern "C" void kernel_launch(void* const* d_in, const int* in_sizes, int n_in,
                              void* d_out, int out_size) {
    (void)in_sizes; (void)n_in; (void)out_size;
    const float* token_val   = (const float*)d_in[0];
    const float* token_state = (const float*)d_in[1];
    const float* init_state  = (const float*)d_in[2];
    const float* init_val    = (const float*)d_in[3];
    const float* rUs_w = (const float*)d_in[4];
    const float* rUs_b = (const float*)d_in[5];
    const float* rUt_w = (const float*)d_in[6];
    const float* rUt_b = (const float*)d_in[7];
    const float* r_w   = (const float*)d_in[8];
    const float* pUs_w = (const float*)d_in[9];
    const float* pUs_b = (const float*)d_in[10];
    const float* pUt_w = (const float*)d_in[11];
    const float* pUt_b = (const float*)d_in[12];
    const float* p_w   = (const float*)d_in[13];
    const float* ln_g  = (const float*)d_in[14];
    const float* ln_b  = (const float*)d_in[15];
    float* out = (float*)d_out;

    float *p_mv0, *p_pt2, *p_ps, *p_mv1, *p_qt, *p_qs2, *p_st0, *p_st1raw, *p_st1;
    cudaGetSymbolAddress((void**)&p_mv0, g_mem_val0);
    cudaGetSymbolAddress((void**)&p_pt2, g_pt2);
    cudaGetSymbolAddress((void**)&p_ps, g_ps);
    cudaGetSymbolAddress((void**)&p_mv1, g_mem_val1);
    cudaGetSymbolAddress((void**)&p_qt, g_qt);
    cudaGetSymbolAddress((void**)&p_qs2, g_qs2);
    cudaGetSymbolAddress((void**)&p_st0, g_mem_state0);
    cudaGetSymbolAddress((void**)&p_st1raw, g_state1_raw);
    cudaGetSymbolAddress((void**)&p_st1, g_state1);

    // mem_val0 = LN(init_val)  (batch independent)
    ln_rows_kernel<<<Mm, 256>>>(init_val, p_mv0, ln_g, ln_b);
    // mem_state0 = signed_softmax_state(init_state)
    sss_kernel<<<1, 256>>>(init_state, p_st0);
    // pt2 = (mem_val0 @ rUt + b) * r_w * 0.1   (256 rows -> RT=32, 8 blocks)
    gemm_proj<32><<<dim3(Mm / 32, 1), 256>>>(p_mv0,
        p_pt2, rUt_w, rUt_b, r_w, nullptr,
        nullptr, nullptr, nullptr, nullptr, nullptr);
    // ps = token_val @ rUs + b   (32768 rows -> RT=128, 256 blocks)
    gemm_proj<128><<<dim3((Bb * Ss) / 128, 1), 256>>>(token_val,
        p_ps, rUs_w, rUs_b, nullptr, nullptr,
        nullptr, nullptr, nullptr, nullptr, nullptr);
    // scores = pt2 . ps
    scores2_kernel<<<dim3(Ss / 128, Mm / 128, Bb), 256>>>();
    // write phase: topk + edges + gather-add + LN; also raw state update
    write_kernel<<<Bb * Mm, 256>>>(token_val, token_state, ln_g, ln_b);
    // state1 = signed_softmax_state(state1_raw)
    sss_kernel<<<Bb, 256>>>(p_st1raw, p_st1);
    // fused: y=0 -> qt = (mem_val1 @ pUt + b) * p_w * 0.1
    //        y=1 -> qs2 = (mem_val1 @ pUs + b) * state1[row]
    gemm_proj<32><<<dim3((Bb * Mm) / 32, 2), 256>>>(p_mv1,
        p_qt, pUt_w, pUt_b, p_w, nullptr,
        p_qs2, pUs_w, pUs_b, nullptr, p_st1);
    // propagation + final LN -> out
    prop_kernel<<<Bb * Mm, 256>>>(out, ln_g, ln_b);
}